// round 16
// baseline (speedup 1.0000x reference)
#include <cuda_runtime.h>

// ModifiedLogicSegLoss: loss = sum_{b,c} w[c] * (softplus(x) - t*x)
//   w[c] = sum_l La[l,c]*lam[l] / 128   (levels partition classes; clamp never fires)
// B=262144, C=128 -> 2^23 float4 vectors per input array.
// R13 form at coarser CTA granularity: 512 blocks x 512 threads (same 2048
// threads/SM at regs=32, 4 CTA/SM) -> half the CTA prologues/epilogues and
// half the completion-ticket arrivals, identical per-thread mainloop.

#define NBLOCKS   512
#define NTHREADS  512
#define NC        128
#define NVEC      (1u << 23)                       // 8,388,608 float4 elements
#define STRIDE    (NBLOCKS * NTHREADS)             // 262144, multiple of 32
#define ITERS     (NVEC / STRIDE)                  // 32, compile-time

__device__ float g_partials[NBLOCKS];
__device__ unsigned int g_done = 0;                // re-armed by last block

__device__ __forceinline__ unsigned ticket_acq_rel(unsigned int* p) {
    unsigned old;
    asm volatile("atom.global.add.acq_rel.gpu.u32 %0, [%1], 1;"
                 : "=r"(old) : "l"(p) : "memory");
    return old;
}

__device__ __forceinline__ float bce_elem(float x, float t) {
    // softplus(x) - t*x, stable form: max(x,0) + log1p(exp(-|x|))
    float e  = __expf(-fabsf(x));
    float sp = fmaxf(x, 0.0f) + __logf(1.0f + e);
    return fmaf(-t, x, sp);
}

__global__ void __launch_bounds__(NTHREADS, 4)
loss_fused(const float4* __restrict__ yp, const float4* __restrict__ yt,
           const float*  __restrict__ La, const float*  __restrict__ lam,
           float* __restrict__ out) {
    __shared__ float wred[NTHREADS / 32];          // 16 warp sums
    __shared__ bool s_last;
    const int tid = threadIdx.x;
    const unsigned gid = blockIdx.x * NTHREADS + tid;

    // Per-thread weight quad for classes 4q..4q+3 (q = gid & 31). All
    // addresses are identical across CTAs -> L2-hot broadcast. No smem,
    // no barrier: streaming loads below can be scheduled ahead of this.
    const int c0 = (gid & 31) * 4;
    float4 wv;
    {
        const float l0 = lam[0], l1 = lam[1], l2 = lam[2], l3 = lam[3];
        float wq[4];
        #pragma unroll
        for (int j = 0; j < 4; ++j) {
            float a =        La[0 * NC + c0 + j] * l0;
            a = fmaf(La[1 * NC + c0 + j], l1, a);
            a = fmaf(La[2 * NC + c0 + j], l2, a);
            a = fmaf(La[3 * NC + c0 + j], l3, a);
            wq[j] = a * (1.0f / (float)NC);
        }
        wv = make_float4(wq[0], wq[1], wq[2], wq[3]);
    }

    float acc = 0.0f;
    #pragma unroll
    for (int i = 0; i < ITERS; ++i) {              // fully unrolled (32x)
        const unsigned v = gid + (unsigned)i * STRIDE;
        const float4 x = __ldcs(yp + v);           // streaming: evict-first
        const float4 t = __ldcs(yt + v);
        float s =      wv.x * bce_elem(x.x, t.x);
        s = fmaf(wv.y, bce_elem(x.y, t.y), s);
        s = fmaf(wv.z, bce_elem(x.z, t.z), s);
        s = fmaf(wv.w, bce_elem(x.w, t.w), s);
        acc += s;
    }

    // Intra-block reduce: warp shfl, then warp 0 folds the 16 warp sums.
    #pragma unroll
    for (int o = 16; o > 0; o >>= 1)
        acc += __shfl_xor_sync(0xffffffffu, acc, o);
    if ((tid & 31) == 0) wred[tid >> 5] = acc;
    __syncthreads();

    if (tid < 32) {
        float a = (tid < NTHREADS / 32) ? wred[tid] : 0.0f;
        #pragma unroll
        for (int o = 8; o > 0; o >>= 1)
            a += __shfl_xor_sync(0xffffffffu, a, o);
        if (tid == 0) {
            g_partials[blockIdx.x] = a;
            // acq_rel ticket: release orders the partial store before the
            // increment; the winner's acquire covers its subsequent reads.
            unsigned old = ticket_acq_rel(&g_done);
            s_last = (old == NBLOCKS - 1);
        }
    }
    __syncthreads();

    // Last-arriving block performs the fixed-order final reduction.
    if (s_last) {
        __shared__ float fin[NTHREADS / 32];
        // 512 partials = 128 float4: threads 0..127 read one each, fixed
        // order, L1-bypass (__ldcg) to see other SMs' published values.
        float a = 0.0f;
        if (tid < NBLOCKS / 4) {
            const float4 p = __ldcg(reinterpret_cast<const float4*>(g_partials) + tid);
            a = ((p.x + p.y) + (p.z + p.w));
        }
        #pragma unroll
        for (int o = 16; o > 0; o >>= 1)
            a += __shfl_xor_sync(0xffffffffu, a, o);
        if ((tid & 31) == 0) wred[tid >> 5] = a;   // reuse wred for final fold
        if (tid == 0) g_done = 0u;                 // re-arm for next replay
        __syncthreads();

        if (tid < 32) {
            float b = (tid < 4) ? wred[tid] : 0.0f;   // only warps 0-3 contributed
            #pragma unroll
            for (int o = 2; o > 0; o >>= 1)
                b += __shfl_xor_sync(0xffffffffu, b, o);
            if (tid == 0) out[0] = b;
        }
        (void)fin;
    }
}

extern "C" void kernel_launch(void* const* d_in, const int* in_sizes, int n_in,
                              void* d_out, int out_size) {
    (void)in_sizes; (void)n_in; (void)out_size;
    loss_fused<<<NBLOCKS, NTHREADS>>>(
        (const float4*)d_in[0], (const float4*)d_in[1],
        (const float*)d_in[2],  (const float*)d_in[3],
        (float*)d_out);
}

// round 17
// speedup vs baseline: 1.0274x; 1.0274x over previous
#include <cuda_runtime.h>

// ModifiedLogicSegLoss: loss = sum_{b,c} w[c] * (softplus(x) - t*x)
//   w[c] = sum_l La[l,c]*lam[l] / 128   (levels partition classes; clamp never fires)
// B=262144, C=128 -> 2^23 float4 vectors per input array.
//
// FINAL KERNEL (R13 form). ~45.6us = ~6.1 TB/s sustained dual-stream read,
// >=95% of achievable HBM bandwidth on GB300 for this pattern.
// Established empirically over 16 rounds:
//  - bandwidth tracks resident warps; regs must stay <=32 (8 CTA/SM).
//    SW pipelines / cp.async / LDG.256 / wider reg budgets all regressed.
//  - gid-major indexing makes each unrolled iteration a grid-wide contiguous
//    4MB sweep -> DRAM page locality already optimal.
//  - fused single-launch reduction with an acq_rel ticket beats a second
//    launch (~6.5us) and beats __threadfence (CCTL.IVALL on sm_103a).

#define NBLOCKS   1024
#define NTHREADS  256
#define NC        128
#define NVEC      (1u << 23)                       // 8,388,608 float4 elements
#define STRIDE    (NBLOCKS * NTHREADS)             // 262144, multiple of 32
#define ITERS     (NVEC / STRIDE)                  // 32, compile-time

__device__ float g_partials[NBLOCKS];
__device__ unsigned int g_done = 0;                // re-armed by last block

__device__ __forceinline__ unsigned ticket_acq_rel(unsigned int* p) {
    unsigned old;
    asm volatile("atom.global.add.acq_rel.gpu.u32 %0, [%1], 1;"
                 : "=r"(old) : "l"(p) : "memory");
    return old;
}

__device__ __forceinline__ float bce_elem(float x, float t) {
    // softplus(x) - t*x, stable form: max(x,0) + log1p(exp(-|x|))
    float e  = __expf(-fabsf(x));
    float sp = fmaxf(x, 0.0f) + __logf(1.0f + e);
    return fmaf(-t, x, sp);
}

__global__ void __launch_bounds__(NTHREADS, 8)
loss_fused(const float4* __restrict__ yp, const float4* __restrict__ yt,
           const float*  __restrict__ La, const float*  __restrict__ lam,
           float* __restrict__ out) {
    __shared__ float wred[NTHREADS / 32];
    __shared__ bool s_last;
    const int tid = threadIdx.x;
    const unsigned gid = blockIdx.x * NTHREADS + tid;

    // Per-thread weight quad for classes 4q..4q+3 (q = gid & 31). All
    // addresses are identical across CTAs -> L2-hot broadcast. No smem,
    // no barrier: streaming loads below can be scheduled ahead of this.
    const int c0 = (gid & 31) * 4;
    float4 wv;
    {
        const float l0 = lam[0], l1 = lam[1], l2 = lam[2], l3 = lam[3];
        float wq[4];
        #pragma unroll
        for (int j = 0; j < 4; ++j) {
            float a =        La[0 * NC + c0 + j] * l0;
            a = fmaf(La[1 * NC + c0 + j], l1, a);
            a = fmaf(La[2 * NC + c0 + j], l2, a);
            a = fmaf(La[3 * NC + c0 + j], l3, a);
            wq[j] = a * (1.0f / (float)NC);
        }
        wv = make_float4(wq[0], wq[1], wq[2], wq[3]);
    }

    float acc = 0.0f;
    #pragma unroll
    for (int i = 0; i < ITERS; ++i) {              // fully unrolled (32x)
        const unsigned v = gid + (unsigned)i * STRIDE;
        const float4 x = __ldcs(yp + v);           // streaming: evict-first
        const float4 t = __ldcs(yt + v);
        float s =      wv.x * bce_elem(x.x, t.x);
        s = fmaf(wv.y, bce_elem(x.y, t.y), s);
        s = fmaf(wv.z, bce_elem(x.z, t.z), s);
        s = fmaf(wv.w, bce_elem(x.w, t.w), s);
        acc += s;
    }

    // Intra-block reduce: warp shfl, then warp 0 folds the 8 warp sums.
    #pragma unroll
    for (int o = 16; o > 0; o >>= 1)
        acc += __shfl_xor_sync(0xffffffffu, acc, o);
    if ((tid & 31) == 0) wred[tid >> 5] = acc;
    __syncthreads();

    if (tid < 32) {
        float a = (tid < NTHREADS / 32) ? wred[tid] : 0.0f;
        #pragma unroll
        for (int o = 4; o > 0; o >>= 1)
            a += __shfl_xor_sync(0xffffffffu, a, o);
        if (tid == 0) {
            g_partials[blockIdx.x] = a;
            // acq_rel ticket: release orders the partial store before the
            // increment; the winner's acquire covers its subsequent reads.
            unsigned old = ticket_acq_rel(&g_done);
            s_last = (old == NBLOCKS - 1);
        }
    }
    __syncthreads();

    // Last-arriving block performs the fixed-order final reduction.
    if (s_last) {
        __shared__ float fin[NTHREADS / 32];
        // 1024 partials = 256 float4: one per thread, fixed order, L1-bypass.
        const float4 p = __ldcg(reinterpret_cast<const float4*>(g_partials) + tid);
        float a = ((p.x + p.y) + (p.z + p.w));
        #pragma unroll
        for (int o = 16; o > 0; o >>= 1)
            a += __shfl_xor_sync(0xffffffffu, a, o);
        if ((tid & 31) == 0) fin[tid >> 5] = a;
        if (tid == 0) g_done = 0u;                 // re-arm for next replay
        __syncthreads();

        if (tid < 32) {
            float b = (tid < NTHREADS / 32) ? fin[tid] : 0.0f;
            #pragma unroll
            for (int o = 4; o > 0; o >>= 1)
                b += __shfl_xor_sync(0xffffffffu, b, o);
            if (tid == 0) out[0] = b;
        }
    }
}

extern "C" void kernel_launch(void* const* d_in, const int* in_sizes, int n_in,
                              void* d_out, int out_size) {
    (void)in_sizes; (void)n_in; (void)out_size;
    loss_fused<<<NBLOCKS, NTHREADS>>>(
        (const float4*)d_in[0], (const float4*)d_in[1],
        (const float*)d_in[2],  (const float*)d_in[3],
        (float*)d_out);
}